// round 16
// baseline (speedup 1.0000x reference)
#include <cuda_runtime.h>

// TransOp_expm via traceless Cayley-Hamilton, SCALAR fp32, one batch/thread
// per iteration. R16: DEPTH-2 software prefetch (2x-unrolled grid-stride,
// two live load buffers — load->use distance ~2 iterations covers DRAM
// latency), NSQ=2 / NORD=10.

#define NSQ 2
#define NORD 10

struct Ld { float c0, c1, c2, c3, c4, c5, x0, x1, x2; };

__device__ __forceinline__ Ld load_batch(const float* __restrict__ c,
                                         const float* __restrict__ x, int b) {
    Ld L;
    const float2* cq = (const float2*)(c + b * 6);
    float2 a = __ldg(&cq[0]);
    float2 d = __ldg(&cq[1]);
    float2 e = __ldg(&cq[2]);
    L.c0 = a.x; L.c1 = a.y; L.c2 = d.x; L.c3 = d.y; L.c4 = e.x; L.c5 = e.y;
    const float* xb = x + b * 3;
    L.x0 = __ldg(&xb[0]); L.x1 = __ldg(&xb[1]); L.x2 = __ldg(&xb[2]);
    return L;
}

__device__ __forceinline__ void expm_body(
    const float* __restrict__ s_psi, const Ld& L,
    float* __restrict__ out, int b)
{
    float v0 = L.x0, v1 = L.x1, v2 = L.x2;

    // ---- A = sum_m c_m * psi_scaled[m] ----
    float A0, A1, A2, A3, A4, A5, A6, A7, A8;
    {
        const float4* pr = (const float4*)s_psi;
        float4 p0 = pr[0], p1 = pr[1];
        float  p8 = s_psi[8];
        A0 = L.c0 * p0.x; A1 = L.c0 * p0.y; A2 = L.c0 * p0.z; A3 = L.c0 * p0.w;
        A4 = L.c0 * p1.x; A5 = L.c0 * p1.y; A6 = L.c0 * p1.z; A7 = L.c0 * p1.w;
        A8 = L.c0 * p8;
        float cms[5] = {L.c1, L.c2, L.c3, L.c4, L.c5};
        #pragma unroll
        for (int m = 1; m < 6; m++) {
            float4 q0 = pr[m * 3 + 0];
            float4 q1 = pr[m * 3 + 1];
            float  q8 = s_psi[m * 12 + 8];
            float cmm = cms[m - 1];
            A0 = fmaf(cmm, q0.x, A0); A1 = fmaf(cmm, q0.y, A1);
            A2 = fmaf(cmm, q0.z, A2); A3 = fmaf(cmm, q0.w, A3);
            A4 = fmaf(cmm, q1.x, A4); A5 = fmaf(cmm, q1.y, A5);
            A6 = fmaf(cmm, q1.z, A6); A7 = fmaf(cmm, q1.w, A7);
            A8 = fmaf(cmm, q8,   A8);
        }
    }

    // ---- trace prefactor + traceless shift ----
    float c1 = A0 + A4 + A8;
    float emu = __expf(c1 * ((float)(1 << NSQ) / 3.0f));
    float mu = c1 * (1.0f / 3.0f);
    A0 -= mu; A4 -= mu; A8 -= mu;

    // ---- invariants of traceless Ab ----
    float tt = fmaf(A2, A6, A1 * A3);
    tt = fmaf(A5, A7, tt);
    float ss = fmaf(A4, A4, A0 * A0);
    ss = fmaf(A8, A8, ss);
    float nc2 = fmaf(ss, 0.5f, tt);             // -c2 = tr(Ab^2)/2

    float m0  = fmaf(A4, A8, -(A5 * A7));
    float m1n = fmaf(A5, A6, -(A3 * A8));
    float m2  = fmaf(A3, A7, -(A4 * A6));
    float c3  = fmaf(A0, m0, fmaf(A1, m1n, A2 * m2));   // det(Ab)

    // ---- matvecs (A dies after this) ----
    float w0 = fmaf(A0, v0, fmaf(A1, v1, A2 * v2));
    float w1 = fmaf(A3, v0, fmaf(A4, v1, A5 * v2));
    float w2 = fmaf(A6, v0, fmaf(A7, v1, A8 * v2));
    float u0 = fmaf(A0, w0, fmaf(A1, w1, A2 * w2));
    float u1 = fmaf(A3, w0, fmaf(A4, w1, A5 * w2));
    float u2 = fmaf(A6, w0, fmaf(A7, w1, A8 * w2));

    // ---- Horner Taylor (traceless): E = sa I + sb Ab + sc Ab^2 ----
    const float invfact[NORD + 1] = {
        1.f, 1.f, 0.5f, 1.f/6.f, 1.f/24.f, 1.f/120.f, 1.f/720.f,
        1.f/5040.f, 1.f/40320.f, 1.f/362880.f, 1.f/3628800.f
    };
    float sa = invfact[NORD], sb = 0.0f, sc = 0.0f;
    #pragma unroll
    for (int k = NORD - 1; k >= 0; k--) {
        float oc = sc;
        float na = fmaf(c3,  oc, invfact[k]);
        float nb = fmaf(nc2, oc, sa);
        sc = sb;
        sa = na;
        sb = nb;
    }

    // ---- squarings (Ab^3 = nc2 Ab + c3 I) ----
    #pragma unroll
    for (int sq = 0; sq < NSQ; sq++) {
        float bc2 = 2.0f * (sb * sc);
        float cc  = sc * sc;
        float ab2 = 2.0f * (sa * sb);
        float ac2 = 2.0f * (sa * sc);
        float na  = fmaf(bc2, c3, sa * sa);
        float nb  = fmaf(cc, c3, fmaf(bc2, nc2, ab2));
        float ncc = fmaf(cc, nc2, fmaf(sb, sb, ac2));
        sa = na; sb = nb; sc = ncc;
    }

    // ---- y = emu * (sa v + sb w + sc u) ----
    sa *= emu; sb *= emu; sc *= emu;
    float* ob = out + b * 3;
    ob[0] = fmaf(sa, v0, fmaf(sb, w0, sc * u0));
    ob[1] = fmaf(sa, v1, fmaf(sb, w1, sc * u1));
    ob[2] = fmaf(sa, v2, fmaf(sb, w2, sc * u2));
}

__global__ __launch_bounds__(256, 4) void expmsc16_kernel(
    const float* __restrict__ x,
    const float* __restrict__ c,
    const float* __restrict__ psi,
    float* __restrict__ out,
    int B)
{
    // psi pre-scaled by 1/2^NSQ; rows padded to 12 floats (16B-aligned)
    __shared__ __align__(16) float s_psi[72];
    if (threadIdx.x < 72) {
        int row = threadIdx.x / 12, col = threadIdx.x % 12;
        s_psi[threadIdx.x] =
            (col < 9) ? psi[row * 9 + col] * (1.0f / (float)(1 << NSQ)) : 0.0f;
    }
    __syncthreads();

    const int s = gridDim.x * blockDim.x;
    int b0 = blockIdx.x * blockDim.x + threadIdx.x;
    if (b0 >= B) return;

    // ---- prime two buffers ----
    Ld L0 = load_batch(c, x, b0);
    int b1 = b0 + s;
    bool has1 = (b1 < B);
    Ld L1 = has1 ? load_batch(c, x, b1) : L0;

    while (true) {
        // ---- slot 0: consume L0 (batch b0), prefetch b0+2s into L0 ----
        {
            Ld cur = L0;
            int bp = b0 + 2 * s;
            L0 = load_batch(c, x, (bp < B) ? bp : b0);
            expm_body(s_psi, cur, out, b0);
        }
        if (!has1) break;

        // ---- slot 1: consume L1 (batch b1), prefetch b1+2s into L1 ----
        {
            Ld cur = L1;
            int bp = b1 + 2 * s;
            L1 = load_batch(c, x, (bp < B) ? bp : b1);
            expm_body(s_psi, cur, out, b1);
        }

        b0 += 2 * s;
        b1 += 2 * s;
        if (b0 >= B) break;
        has1 = (b1 < B);
    }
}

extern "C" void kernel_launch(void* const* d_in, const int* in_sizes, int n_in,
                              void* d_out, int out_size) {
    const float* x   = (const float*)d_in[0];  // [B,3,1]
    const float* c   = (const float*)d_in[1];  // [B,6]
    const float* psi = (const float*)d_in[2];  // [6,3,3]
    float* out = (float*)d_out;                // [B,3]

    int B = in_sizes[0] / 3;
    int threads = 256;
    int blocks = 148 * 4;                      // one resident wave at 4 CTA/SM
    int needed = (B + threads - 1) / threads;
    if (needed < blocks) blocks = needed;
    expmsc16_kernel<<<blocks, threads>>>(x, c, psi, out, B);
}

// round 17
// speedup vs baseline: 2.2410x; 2.2410x over previous
#include <cuda_runtime.h>

// TransOp_expm via traceless Cayley-Hamilton, SCALAR fp32, one batch/thread
// per iteration, single-wave grid-stride + depth-1 software prefetch
// (R15 structure — depth-2 spilled at 64 regs and regressed 2.3x).
// NSQ=2, ORDER=10 (remainder ~9e-5 worst-case; measured rel_err is fp32-
// rounding dominated at 9.25e-6, verified at this order in R16).

#define NSQ 2
#define NORD 10

__global__ __launch_bounds__(256, 6) void expmsc17_kernel(
    const float* __restrict__ x,
    const float* __restrict__ c,
    const float* __restrict__ psi,
    float* __restrict__ out,
    int B)
{
    // psi pre-scaled by 1/2^NSQ; rows padded to 12 floats (16B-aligned)
    __shared__ __align__(16) float s_psi[72];
    if (threadIdx.x < 72) {
        int row = threadIdx.x / 12, col = threadIdx.x % 12;
        s_psi[threadIdx.x] =
            (col < 9) ? psi[row * 9 + col] * (1.0f / (float)(1 << NSQ)) : 0.0f;
    }
    __syncthreads();

    const int stride = gridDim.x * blockDim.x;
    int b = blockIdx.x * blockDim.x + threadIdx.x;
    if (b >= B) return;

    // ---- prime: loads for first batch ----
    float2 ld_c0, ld_c1, ld_c2;
    float  ld_x0, ld_x1, ld_x2;
    {
        const float2* cq = (const float2*)(c + b * 6);
        ld_c0 = __ldg(&cq[0]);
        ld_c1 = __ldg(&cq[1]);
        ld_c2 = __ldg(&cq[2]);
        const float* xb = x + b * 3;
        ld_x0 = __ldg(&xb[0]); ld_x1 = __ldg(&xb[1]); ld_x2 = __ldg(&xb[2]);
    }

    while (true) {
        int pn = b + stride;
        bool has_next = (pn < B);
        int pc = has_next ? pn : b;     // clamp: harmless reload of current

        // ---- consume current into locals ----
        float cm0 = ld_c0.x, cm1 = ld_c0.y, cm2 = ld_c1.x;
        float cm3 = ld_c1.y, cm4 = ld_c2.x, cm5 = ld_c2.y;
        float v0 = ld_x0, v1 = ld_x1, v2 = ld_x2;

        // ---- prefetch next iteration (overlaps all compute below) ----
        {
            const float2* cq = (const float2*)(c + pc * 6);
            ld_c0 = __ldg(&cq[0]);
            ld_c1 = __ldg(&cq[1]);
            ld_c2 = __ldg(&cq[2]);
            const float* xb = x + pc * 3;
            ld_x0 = __ldg(&xb[0]); ld_x1 = __ldg(&xb[1]); ld_x2 = __ldg(&xb[2]);
        }

        // ---- A = sum_m c_m * psi_scaled[m] ----
        float A0, A1, A2, A3, A4, A5, A6, A7, A8;
        {
            const float4* pr = (const float4*)s_psi;
            float4 p0 = pr[0], p1 = pr[1];
            float  p8 = s_psi[8];
            A0 = cm0 * p0.x; A1 = cm0 * p0.y; A2 = cm0 * p0.z; A3 = cm0 * p0.w;
            A4 = cm0 * p1.x; A5 = cm0 * p1.y; A6 = cm0 * p1.z; A7 = cm0 * p1.w;
            A8 = cm0 * p8;
            float cms[5] = {cm1, cm2, cm3, cm4, cm5};
            #pragma unroll
            for (int m = 1; m < 6; m++) {
                float4 q0 = pr[m * 3 + 0];
                float4 q1 = pr[m * 3 + 1];
                float  q8 = s_psi[m * 12 + 8];
                float cmm = cms[m - 1];
                A0 = fmaf(cmm, q0.x, A0); A1 = fmaf(cmm, q0.y, A1);
                A2 = fmaf(cmm, q0.z, A2); A3 = fmaf(cmm, q0.w, A3);
                A4 = fmaf(cmm, q1.x, A4); A5 = fmaf(cmm, q1.y, A5);
                A6 = fmaf(cmm, q1.z, A6); A7 = fmaf(cmm, q1.w, A7);
                A8 = fmaf(cmm, q8,   A8);
            }
        }

        // ---- trace prefactor + traceless shift ----
        float c1 = A0 + A4 + A8;
        float emu = __expf(c1 * ((float)(1 << NSQ) / 3.0f));
        float mu = c1 * (1.0f / 3.0f);
        A0 -= mu; A4 -= mu; A8 -= mu;

        // ---- invariants of traceless Ab ----
        float tt = fmaf(A2, A6, A1 * A3);
        tt = fmaf(A5, A7, tt);
        float ss = fmaf(A4, A4, A0 * A0);
        ss = fmaf(A8, A8, ss);
        float nc2 = fmaf(ss, 0.5f, tt);             // -c2 = tr(Ab^2)/2

        float m0  = fmaf(A4, A8, -(A5 * A7));
        float m1n = fmaf(A5, A6, -(A3 * A8));
        float m2  = fmaf(A3, A7, -(A4 * A6));
        float c3  = fmaf(A0, m0, fmaf(A1, m1n, A2 * m2));   // det(Ab)

        // ---- matvecs (A dies after this) ----
        float w0 = fmaf(A0, v0, fmaf(A1, v1, A2 * v2));
        float w1 = fmaf(A3, v0, fmaf(A4, v1, A5 * v2));
        float w2 = fmaf(A6, v0, fmaf(A7, v1, A8 * v2));
        float u0 = fmaf(A0, w0, fmaf(A1, w1, A2 * w2));
        float u1 = fmaf(A3, w0, fmaf(A4, w1, A5 * w2));
        float u2 = fmaf(A6, w0, fmaf(A7, w1, A8 * w2));

        // ---- Horner Taylor (traceless): E = sa I + sb Ab + sc Ab^2 ----
        const float invfact[NORD + 1] = {
            1.f, 1.f, 0.5f, 1.f/6.f, 1.f/24.f, 1.f/120.f, 1.f/720.f,
            1.f/5040.f, 1.f/40320.f, 1.f/362880.f, 1.f/3628800.f
        };
        float sa = invfact[NORD], sb = 0.0f, sc = 0.0f;
        #pragma unroll
        for (int k = NORD - 1; k >= 0; k--) {
            float oc = sc;
            float na = fmaf(c3,  oc, invfact[k]);
            float nb = fmaf(nc2, oc, sa);
            sc = sb;
            sa = na;
            sb = nb;
        }

        // ---- squarings (Ab^3 = nc2 Ab + c3 I) ----
        #pragma unroll
        for (int sq = 0; sq < NSQ; sq++) {
            float bc2 = 2.0f * (sb * sc);
            float cc  = sc * sc;
            float ab2 = 2.0f * (sa * sb);
            float ac2 = 2.0f * (sa * sc);
            float na  = fmaf(bc2, c3, sa * sa);
            float nb  = fmaf(cc, c3, fmaf(bc2, nc2, ab2));
            float ncc = fmaf(cc, nc2, fmaf(sb, sb, ac2));
            sa = na; sb = nb; sc = ncc;
        }

        // ---- y = emu * (sa v + sb w + sc u) ----
        sa *= emu; sb *= emu; sc *= emu;
        float* ob = out + b * 3;
        ob[0] = fmaf(sa, v0, fmaf(sb, w0, sc * u0));
        ob[1] = fmaf(sa, v1, fmaf(sb, w1, sc * u1));
        ob[2] = fmaf(sa, v2, fmaf(sb, w2, sc * u2));

        if (!has_next) break;
        b = pn;
    }
}

extern "C" void kernel_launch(void* const* d_in, const int* in_sizes, int n_in,
                              void* d_out, int out_size) {
    const float* x   = (const float*)d_in[0];  // [B,3,1]
    const float* c   = (const float*)d_in[1];  // [B,6]
    const float* psi = (const float*)d_in[2];  // [6,3,3]
    float* out = (float*)d_out;                // [B,3]

    int B = in_sizes[0] / 3;
    int threads = 256;
    int blocks = 148 * 6;                      // one resident wave at 6 CTA/SM
    int needed = (B + threads - 1) / threads;
    if (needed < blocks) blocks = needed;
    expmsc17_kernel<<<blocks, threads>>>(x, c, psi, out, B);
}